// round 16
// baseline (speedup 1.0000x reference)
#include <cuda_runtime.h>
#include <cuda_fp16.h>
#include <math.h>
#include <stdint.h>

#define N_NODES 50000
#define N_EDGES 800000
#define N_GRAPHS 512
#define D_IN 128
#define D_EDGE 32
#define D_HID 128
#define D_GLOB 64
#define K1 288

#define TILE_E 64                  /* edge tile per warp-group */
#define NT (N_EDGES / TILE_E)      /* 12500 tiles */
#define TILE_N 64                  /* node tile per warp-group */
#define NTN ((N_NODES + TILE_N - 1) / TILE_N)  /* 782 */
#define EDGE_GRID 148
#define ETHREADS 512               /* 2 groups x 8 warps (2 wm x 4 wn, 32x32) */
#define NSTREAMS (EDGE_GRID * 2)   /* 296 tile streams */

#define A_STRIDE 296               /* halves: 592 B rows */
#define H_STRIDE 136               /* halves: 272 B rows */

// ---- scratch ----
__device__ float  g_agg[N_NODES * D_HID];
__device__ float  g_pooled[N_GRAPHS * D_HID];
__device__ float  g_counts[N_GRAPHS];
__device__ __half g_xh[N_NODES * D_IN];
// fp16 weight images: byte(k,n) = k*256 + (((n>>3)^(k&7))*16) + (n&7)*2
__device__ __half g_B1h[K1 * D_HID];
__device__ __half g_B2h[D_HID * D_HID];
__device__ __half g_Bgh[2 * D_HID * D_HID];
__device__ __half g_Bnh[2 * D_HID * D_HID];

// ---- edge kernel SMEM layout (bytes) ----
#define E_IDX   0                          /* 2 groups x 2 bufs x 128 ints = 2048 */
#define E_BE1   2048
#define E_BE2   2560
#define E_A     3072                       /* 2 groups x 64 x 592 = 75776 */
#define E_H     (E_A + 75776)              /* 78848: 2 groups x 64 x 272 = 34816 */
#define E_W1    (E_H + 34816)              /* 113664: 73728 */
#define E_W2    (E_W1 + 73728)             /* 187392: 32768 */
#define E_TOTAL (E_W2 + 32768)             /* 220160 */

#define A_GRP 37888
#define H_GRP 17408

// ---- node kernel SMEM layout (persistent) ----
#define N_BG    0
#define N_BN    512
#define N_A     1024                       /* 2 groups x 64 x 592 = 75776 */
#define N_WG    (N_A + 75776)
#define N_WN    (N_WG + 65536)
#define N_POOL  (N_WN + 65536)             /* 207872: 2 groups x 8 x 128 f32 = 8192 */
#define N_TOTAL (N_POOL + 8192)            /* 216064 */

// ---- global kernel ----
#define G_PER_BLK 8
#define G_SMEM ((192 * 64 + G_PER_BLK * 192 + 64) * 4)

// ============================ PTX helpers ===================================
__device__ __forceinline__ uint32_t smem_u32(const void* p) {
    uint32_t a;
    asm("{ .reg .u64 t; cvta.to.shared.u64 t, %1; cvt.u32.u64 %0, t; }" : "=r"(a) : "l"(p));
    return a;
}
__device__ __forceinline__ void barg(int id) {
    asm volatile("bar.sync %0, %1;" :: "r"(id), "r"(256) : "memory");
}
__device__ __forceinline__ void ldm_x4(uint32_t* r, uint32_t addr) {
    asm volatile("ldmatrix.sync.aligned.m8n8.x4.shared.b16 {%0,%1,%2,%3}, [%4];"
                 : "=r"(r[0]), "=r"(r[1]), "=r"(r[2]), "=r"(r[3]) : "r"(addr));
}
__device__ __forceinline__ void ldm_x4_t(uint32_t* r, uint32_t addr) {
    asm volatile("ldmatrix.sync.aligned.m8n8.x4.trans.shared.b16 {%0,%1,%2,%3}, [%4];"
                 : "=r"(r[0]), "=r"(r[1]), "=r"(r[2]), "=r"(r[3]) : "r"(addr));
}
__device__ __forceinline__ void mma16816(float* c, const uint32_t* a, uint32_t b0, uint32_t b1) {
    asm volatile(
        "mma.sync.aligned.m16n8k16.row.col.f32.f16.f16.f32 "
        "{%0,%1,%2,%3}, {%4,%5,%6,%7}, {%8,%9}, {%0,%1,%2,%3};"
        : "+f"(c[0]), "+f"(c[1]), "+f"(c[2]), "+f"(c[3])
        : "r"(a[0]), "r"(a[1]), "r"(a[2]), "r"(a[3]), "r"(b0), "r"(b1));
}
__device__ __forceinline__ void red_add_v4(float* p, float a, float b, float c, float d) {
    asm volatile("red.global.add.v4.f32 [%0], {%1, %2, %3, %4};"
                 :: "l"(p), "f"(a), "f"(b), "f"(c), "f"(d) : "memory");
}
__device__ __forceinline__ void red_add_v2(float* p, float a, float b) {
    asm volatile("red.global.add.v2.f32 [%0], {%1, %2};" :: "l"(p), "f"(a), "f"(b) : "memory");
}
__device__ __forceinline__ void red_add_f(float* p, float a) {
    asm volatile("red.global.add.f32 [%0], %1;" :: "l"(p), "f"(a) : "memory");
}
__device__ __forceinline__ void cpa16(uint32_t dst, const void* src) {
    asm volatile("cp.async.cg.shared.global [%0], [%1], 16;" :: "r"(dst), "l"(src) : "memory");
}
#define CPA_COMMIT() asm volatile("cp.async.commit_group;" ::: "memory")
#define CPA_WAIT0()  asm volatile("cp.async.wait_group 0;" ::: "memory")
__device__ __forceinline__ uint32_t h2_bits(__half2 h) {
    return *reinterpret_cast<uint32_t*>(&h);
}

// ============================================================================
// Prep: zero scratch + fp16-convert x + weight images + counts histogram.
// ============================================================================
__global__ void prep_all(const float* __restrict__ x,
                         const float* __restrict__ We1, const float* __restrict__ We2,
                         const float* __restrict__ Wg,  const float* __restrict__ Wn,
                         const int* __restrict__ batch) {
    int idx = blockIdx.x * blockDim.x + threadIdx.x;
    int stride = gridDim.x * blockDim.x;
    float4 z = make_float4(0.f, 0.f, 0.f, 0.f);
    float4* a4 = (float4*)g_agg;
    for (int i = idx; i < N_NODES * D_HID / 4; i += stride) a4[i] = z;
    for (int i = idx; i < N_GRAPHS * D_HID; i += stride) g_pooled[i] = 0.0f;
    for (int i = idx; i < N_GRAPHS; i += stride) g_counts[i] = 0.0f;

    const int NX = N_NODES * D_IN / 4;
    for (int i = idx; i < NX; i += stride) {
        float4 v = __ldg((const float4*)x + i);
        __half2 h0 = __floats2half2_rn(v.x, v.y), h1 = __floats2half2_rn(v.z, v.w);
        *((uint2*)g_xh + i) = make_uint2(h2_bits(h0), h2_bits(h1));
    }
    for (int i = idx; i < K1 * D_HID; i += stride) {
        int k = i >> 7, n = i & 127;
        uint32_t off = (uint32_t)k * 256 + (((n >> 3) ^ (k & 7)) * 16) + (n & 7) * 2;
        *(__half*)((char*)g_B1h + off) = __float2half_rn(We1[k * D_HID + n]);
    }
    for (int i = idx; i < D_HID * D_HID; i += stride) {
        int k = i >> 7, n = i & 127;
        uint32_t off = (uint32_t)k * 256 + (((n >> 3) ^ (k & 7)) * 16) + (n & 7) * 2;
        *(__half*)((char*)g_B2h + off) = __float2half_rn(We2[k * D_HID + n]);
    }
    for (int i = idx; i < 2 * D_HID * D_HID; i += stride) {
        int k = i >> 7, n = i & 127;
        uint32_t off = (uint32_t)k * 256 + (((n >> 3) ^ (k & 7)) * 16) + (n & 7) * 2;
        *(__half*)((char*)g_Bgh + off) = __float2half_rn(Wg[k * D_HID + n]);
        *(__half*)((char*)g_Bnh + off) = __float2half_rn(Wn[k * D_HID + n]);
    }
    for (int i = idx; i < N_NODES; i += stride)
        red_add_f(&g_counts[batch[i]], 1.0f);
}

// ============================================================================
// Edge block: R15 champion — persistent, 2 independent 8-warp groups, resident
// weights, overlapped cp.async gather with inline ea conversion, v4 scatter.
// ============================================================================
__global__ __launch_bounds__(ETHREADS, 1) void edge_kernel(
    const int* __restrict__ eidx, const float* __restrict__ ea,
    const float* __restrict__ be1, const float* __restrict__ be2)
{
    extern __shared__ char smem[];
    const uint32_t sb = smem_u32(smem);
    const int tid = threadIdx.x, wid = tid >> 5, lane = tid & 31;
    const int grp = tid >> 8;
    const int lwid = wid & 7;
    const int ltid = tid & 255;
    const int wm = lwid & 1, wn = lwid >> 1;
    const int barid = grp + 1;

    int*   sIdx = (int*)(smem + E_IDX + grp * 1024);
    float* sBE1 = (float*)(smem + E_BE1);
    float* sBE2 = (float*)(smem + E_BE2);

    if (tid < D_HID) { sBE1[tid] = be1[tid]; sBE2[tid] = be2[tid]; }

    {
        const uint4* s1 = (const uint4*)g_B1h; uint4* d1 = (uint4*)(smem + E_W1);
        #pragma unroll
        for (int i = 0; i < 9; i++) d1[tid + i * 512] = s1[tid + i * 512];
        const uint4* s2 = (const uint4*)g_B2h; uint4* d2 = (uint4*)(smem + E_W2);
        #pragma unroll
        for (int i = 0; i < 4; i++) d2[tid + i * 512] = s2[tid + i * 512];
    }
    __syncthreads();

    const int lo15 = lane & 15;
    const int hi   = lane >> 4;
    const int lo7  = lane & 7;
    uint32_t bXor[2];
    #pragma unroll
    for (int p = 0; p < 2; p++) bXor[p] = (uint32_t)(((wn * 4 + 2 * p + hi) ^ lo7) * 16);

    const uint32_t aG = sb + E_A + grp * A_GRP;
    const uint32_t hG = sb + E_H + grp * H_GRP;
    const uint32_t aBase0 = aG + ((32 * wm + lo15) * A_STRIDE + hi * 8) * 2;
    const uint32_t aBase1 = aBase0 + 16 * A_STRIDE * 2;
    const uint32_t hBase0 = hG + ((32 * wm + lo15) * H_STRIDE + hi * 8) * 2;
    const uint32_t hBase1 = hBase0 + 16 * H_STRIDE * 2;
    const uint32_t w1Base = sb + E_W1 + lo15 * 256;
    const uint32_t w2Base = sb + E_W2 + lo15 * 256;

    const int rowLo = 32 * wm + (lane >> 2);
    const int colLo = wn * 32 + (lane & 3) * 2;
    const int odd   = lane & 1;
    const int col4  = wn * 32 + ((lane & 3) >> 1) * 4;

    const int eaRow = ltid >> 2, eaSeg = ltid & 3;
    const uint32_t eaDst = (aG - sb) + eaRow * 592 + 512 + eaSeg * 16;

    int t = blockIdx.x * 2 + grp;
    int pb = 0;
    if (ltid < TILE_E)            sIdx[ltid] = eidx[t * TILE_E + ltid];
    else if (ltid < 2 * TILE_E)   sIdx[ltid] = eidx[N_EDGES + t * TILE_E + (ltid - TILE_E)];
    barg(barid);
    {
        const float* ep = ea + (size_t)(t * TILE_E + eaRow) * D_EDGE + eaSeg * 8;
        float4 v0 = __ldg((const float4*)ep);
        float4 v1 = __ldg((const float4*)ep + 1);
        const int* sS = sIdx, *sD = sIdx + TILE_E;
        #pragma unroll
        for (int it = 0; it < 8; it++) {
            int i = ltid + it * 256;
            int row = i >> 5, u = i & 31;
            const void* src = (u < 16) ? (const void*)(g_xh + (size_t)sS[row] * D_IN + u * 8)
                                       : (const void*)(g_xh + (size_t)sD[row] * D_IN + (u - 16) * 8);
            cpa16(aG + row * 592 + u * 16, src);
        }
        CPA_COMMIT();
        *(uint2*)(smem + eaDst) = make_uint2(h2_bits(__floats2half2_rn(v0.x, v0.y)),
                                             h2_bits(__floats2half2_rn(v0.z, v0.w)));
        *(uint2*)(smem + eaDst + 8) = make_uint2(h2_bits(__floats2half2_rn(v1.x, v1.y)),
                                                 h2_bits(__floats2half2_rn(v1.z, v1.w)));
    }

    for (; t < NT; t += NSTREAMS, pb ^= 1) {
        const int tn = t + NSTREAMS;
        if (tn < NT) {
            if (ltid < TILE_E)          sIdx[(pb ^ 1) * 128 + ltid] = eidx[tn * TILE_E + ltid];
            else if (ltid < 2 * TILE_E) sIdx[(pb ^ 1) * 128 + ltid] =
                                            eidx[N_EDGES + tn * TILE_E + (ltid - TILE_E)];
        }
        CPA_WAIT0();
        barg(barid);

        float c[2][4][4];
        #pragma unroll
        for (int mi = 0; mi < 2; mi++)
            #pragma unroll
            for (int nt = 0; nt < 4; nt++)
                #pragma unroll
                for (int j = 0; j < 4; j++) c[mi][nt][j] = 0.0f;

        #pragma unroll
        for (int ks = 0; ks < 18; ks++) {
            uint32_t a0[4], a1[4];
            ldm_x4(a0, aBase0 + ks * 32);
            ldm_x4(a1, aBase1 + ks * 32);
            uint32_t bk = w1Base + ks * 4096;
            #pragma unroll
            for (int p = 0; p < 2; p++) {
                uint32_t b[4];
                ldm_x4_t(b, bk + bXor[p]);
                mma16816(c[0][2 * p + 0], a0, b[0], b[1]);
                mma16816(c[0][2 * p + 1], a0, b[2], b[3]);
                mma16816(c[1][2 * p + 0], a1, b[0], b[1]);
                mma16816(c[1][2 * p + 1], a1, b[2], b[3]);
            }
        }
        barg(barid);

        if (tn < NT) {
            const float* ep = ea + (size_t)(tn * TILE_E + eaRow) * D_EDGE + eaSeg * 8;
            float4 v0 = __ldg((const float4*)ep);
            float4 v1 = __ldg((const float4*)ep + 1);
            const int* sS = sIdx + (pb ^ 1) * 128, *sD = sS + TILE_E;
            #pragma unroll
            for (int it = 0; it < 8; it++) {
                int i = ltid + it * 256;
                int row = i >> 5, u = i & 31;
                const void* src = (u < 16) ? (const void*)(g_xh + (size_t)sS[row] * D_IN + u * 8)
                                           : (const void*)(g_xh + (size_t)sD[row] * D_IN + (u - 16) * 8);
                cpa16(aG + row * 592 + u * 16, src);
            }
            CPA_COMMIT();
            *(uint2*)(smem + eaDst) = make_uint2(h2_bits(__floats2half2_rn(v0.x, v0.y)),
                                                 h2_bits(__floats2half2_rn(v0.z, v0.w)));
            *(uint2*)(smem + eaDst + 8) = make_uint2(h2_bits(__floats2half2_rn(v1.x, v1.y)),
                                                     h2_bits(__floats2half2_rn(v1.z, v1.w)));
        }

        #pragma unroll
        for (int mi = 0; mi < 2; mi++) {
            int r0 = rowLo + 16 * mi;
            #pragma unroll
            for (int nt = 0; nt < 4; nt++) {
                int col = nt * 8 + colLo;
                float2 bb = *(const float2*)(sBE1 + col);
                float v0 = fmaxf(c[mi][nt][0] + bb.x, 0.f);
                float v1 = fmaxf(c[mi][nt][1] + bb.y, 0.f);
                float v2 = fmaxf(c[mi][nt][2] + bb.x, 0.f);
                float v3 = fmaxf(c[mi][nt][3] + bb.y, 0.f);
                *(uint32_t*)(smem + (hG - sb) + (r0 * H_STRIDE + col) * 2) =
                    h2_bits(__floats2half2_rn(v0, v1));
                *(uint32_t*)(smem + (hG - sb) + ((r0 + 8) * H_STRIDE + col) * 2) =
                    h2_bits(__floats2half2_rn(v2, v3));
            }
        }
        barg(barid);

        #pragma unroll
        for (int mi = 0; mi < 2; mi++)
            #pragma unroll
            for (int nt = 0; nt < 4; nt++)
                #pragma unroll
                for (int j = 0; j < 4; j++) c[mi][nt][j] = 0.0f;

        #pragma unroll
        for (int ks = 0; ks < 8; ks++) {
            uint32_t a0[4], a1[4];
            ldm_x4(a0, hBase0 + ks * 32);
            ldm_x4(a1, hBase1 + ks * 32);
            uint32_t bk = w2Base + ks * 4096;
            #pragma unroll
            for (int p = 0; p < 2; p++) {
                uint32_t b[4];
                ldm_x4_t(b, bk + bXor[p]);
                mma16816(c[0][2 * p + 0], a0, b[0], b[1]);
                mma16816(c[0][2 * p + 1], a0, b[2], b[3]);
                mma16816(c[1][2 * p + 0], a1, b[0], b[1]);
                mma16816(c[1][2 * p + 1], a1, b[2], b[3]);
            }
        }

        const int* sDstP = sIdx + pb * 128 + TILE_E;
        #pragma unroll
        for (int mi = 0; mi < 2; mi++) {
            int rT = rowLo + 16 * mi;
            int rB = rT + 8;
            float* dp = g_agg + (size_t)sDstP[odd ? rB : rT] * D_HID;
            #pragma unroll
            for (int nt = 0; nt < 4; nt++) {
                int col = nt * 8 + colLo;
                float2 bb = *(const float2*)(sBE2 + col);
                float t0 = fmaxf(c[mi][nt][0] + bb.x, 0.f);
                float t1 = fmaxf(c[mi][nt][1] + bb.y, 0.f);
                float b0 = fmaxf(c[mi][nt][2] + bb.x, 0.f);
                float b1 = fmaxf(c[mi][nt][3] + bb.y, 0.f);
                float2 send = odd ? make_float2(t0, t1) : make_float2(b0, b1);
                unsigned long long sv = *reinterpret_cast<unsigned long long*>(&send);
                unsigned long long rvu = __shfl_xor_sync(0xffffffffu, sv, 1);
                float2 rv = *reinterpret_cast<float2*>(&rvu);
                if (!odd) red_add_v4(dp + nt * 8 + col4, t0, t1, rv.x, rv.y);
                else      red_add_v4(dp + nt * 8 + col4, rv.x, rv.y, b0, b1);
            }
        }
    }
}

// ============================================================================
// Node block: persistent, 2 groups, resident Wg/Wn, SMEM-staged pooled sums
// (sorted batch => tile spans few graphs; fallback to direct atomics if >=8).
// ============================================================================
__global__ __launch_bounds__(ETHREADS, 1) void node_kernel(
    const int* __restrict__ batch,
    const float* __restrict__ bg, const float* __restrict__ bn,
    float* __restrict__ xw_out)
{
    extern __shared__ char smem[];
    const uint32_t sb = smem_u32(smem);
    const int tid = threadIdx.x, wid = tid >> 5, lane = tid & 31;
    const int grp = tid >> 8;
    const int lwid = wid & 7;
    const int ltid = tid & 255;
    const int wm = lwid & 1, wn = lwid >> 1;
    const int barid = grp + 1;

    float* sBG = (float*)(smem + N_BG);
    float* sBN = (float*)(smem + N_BN);
    float* sPool = (float*)(smem + N_POOL) + grp * 1024;   // 8 graphs x 128
    if (tid < D_HID) { sBG[tid] = bg[tid]; sBN[tid] = bn[tid]; }

    {
        const uint4* sg = (const uint4*)g_Bgh; uint4* dg = (uint4*)(smem + N_WG);
        #pragma unroll
        for (int i = 0; i < 8; i++) dg[tid + i * 512] = sg[tid + i * 512];
        const uint4* sn = (const uint4*)g_Bnh; uint4* dn = (uint4*)(smem + N_WN);
        #pragma unroll
        for (int i = 0; i < 8; i++) dn[tid + i * 512] = sn[tid + i * 512];
    }
    __syncthreads();

    const int lo15 = lane & 15;
    const int hi   = lane >> 4;
    const int lo7  = lane & 7;
    uint32_t bXor[2];
    #pragma unroll
    for (int p = 0; p < 2; p++) bXor[p] = (uint32_t)(((wn * 4 + 2 * p + hi) ^ lo7) * 16);

    const uint32_t aG = sb + N_A + grp * A_GRP;
    const uint32_t aBase0 = aG + ((32 * wm + lo15) * A_STRIDE + hi * 8) * 2;
    const uint32_t aBase1 = aBase0 + 16 * A_STRIDE * 2;
    const uint32_t wgBase = sb + N_WG + lo15 * 256;
    const uint32_t wnBase = sb + N_WN + lo15 * 256;

    const int rowLo = 32 * wm + (lane >> 2);
    const int colLo = wn * 32 + (lane & 3) * 2;

    for (int t = blockIdx.x * 2 + grp; t < NTN; t += NSTREAMS) {
        const int nBase = t * TILE_N;
        const int gmin = batch[min(nBase, N_NODES - 1)];
        const int gmax = batch[min(nBase + TILE_N - 1, N_NODES - 1)];
        const bool fast = (gmax - gmin) < 8;

        #pragma unroll
        for (int it = 0; it < 8; it++) {
            int i = ltid + it * 256;
            int row = i >> 5, u = i & 31;
            int n = min(nBase + row, N_NODES - 1);
            if (u < 16) {
                cpa16(aG + row * 592 + u * 16, g_xh + (size_t)n * D_IN + u * 8);
            } else {
                const float4* ap = (const float4*)(g_agg + (size_t)n * D_HID + (u - 16) * 8);
                float4 v0 = ap[0], v1 = ap[1];
                uint4 o;
                o.x = h2_bits(__floats2half2_rn(v0.x, v0.y));
                o.y = h2_bits(__floats2half2_rn(v0.z, v0.w));
                o.z = h2_bits(__floats2half2_rn(v1.x, v1.y));
                o.w = h2_bits(__floats2half2_rn(v1.z, v1.w));
                *reinterpret_cast<uint4*>(smem + (aG - sb) + row * 592 + u * 16) = o;
            }
        }
        CPA_COMMIT();
        // zero pooled staging (ordered vs prev flush by trailing barg)
        #pragma unroll
        for (int i = 0; i < 4; i++) sPool[ltid + i * 256] = 0.0f;
        CPA_WAIT0();
        barg(barid);   // A ready + sPool zeroed

        float c[2][4][4];
        #pragma unroll
        for (int mi = 0; mi < 2; mi++)
            #pragma unroll
            for (int nt = 0; nt < 4; nt++)
                #pragma unroll
                for (int j = 0; j < 4; j++) c[mi][nt][j] = 0.0f;

        #pragma unroll
        for (int ks = 0; ks < 16; ks++) {
            uint32_t a0[4], a1[4];
            ldm_x4(a0, aBase0 + ks * 32);
            ldm_x4(a1, aBase1 + ks * 32);
            uint32_t bk = wgBase + ks * 4096;
            #pragma unroll
            for (int p = 0; p < 2; p++) {
                uint32_t b[4];
                ldm_x4_t(b, bk + bXor[p]);
                mma16816(c[0][2 * p + 0], a0, b[0], b[1]);
                mma16816(c[0][2 * p + 1], a0, b[2], b[3]);
                mma16816(c[1][2 * p + 0], a1, b[0], b[1]);
                mma16816(c[1][2 * p + 1], a1, b[2], b[3]);
            }
        }

        float gate[2][4][4];
        #pragma unroll
        for (int mi = 0; mi < 2; mi++) {
            int rT = nBase + rowLo + 16 * mi;
            int rB = rT + 8;
            #pragma unroll
            for (int nt = 0; nt < 4; nt++) {
                int col = nt * 8 + colLo;
                float2 bb = *(const float2*)(sBG + col);
                gate[mi][nt][0] = 1.0f / (1.0f + __expf(-(c[mi][nt][0] + bb.x)));
                gate[mi][nt][1] = 1.0f / (1.0f + __expf(-(c[mi][nt][1] + bb.y)));
                gate[mi][nt][2] = 1.0f / (1.0f + __expf(-(c[mi][nt][2] + bb.x)));
                gate[mi][nt][3] = 1.0f / (1.0f + __expf(-(c[mi][nt][3] + bb.y)));
                if (rT < N_NODES)
                    *(float2*)(xw_out + (size_t)rT * D_HID + col) =
                        make_float2(gate[mi][nt][0], gate[mi][nt][1]);
                if (rB < N_NODES)
                    *(float2*)(xw_out + (size_t)rB * D_HID + col) =
                        make_float2(gate[mi][nt][2], gate[mi][nt][3]);
            }
        }

        #pragma unroll
        for (int mi = 0; mi < 2; mi++)
            #pragma unroll
            for (int nt = 0; nt < 4; nt++)
                #pragma unroll
                for (int j = 0; j < 4; j++) c[mi][nt][j] = 0.0f;

        #pragma unroll
        for (int ks = 0; ks < 16; ks++) {
            uint32_t a0[4], a1[4];
            ldm_x4(a0, aBase0 + ks * 32);
            ldm_x4(a1, aBase1 + ks * 32);
            uint32_t bk = wnBase + ks * 4096;
            #pragma unroll
            for (int p = 0; p < 2; p++) {
                uint32_t b[4];
                ldm_x4_t(b, bk + bXor[p]);
                mma16816(c[0][2 * p + 0], a0, b[0], b[1]);
                mma16816(c[0][2 * p + 1], a0, b[2], b[3]);
                mma16816(c[1][2 * p + 0], a1, b[0], b[1]);
                mma16816(c[1][2 * p + 1], a1, b[2], b[3]);
            }
        }

        // x_new epilogue -> SMEM pooled accumulation (or direct fallback)
        #pragma unroll
        for (int mi = 0; mi < 2; mi++) {
            int rT = nBase + rowLo + 16 * mi;
            int rB = rT + 8;
            int bT = batch[min(rT, N_NODES - 1)];
            int bB = batch[min(rB, N_NODES - 1)];
            #pragma unroll
            for (int nt = 0; nt < 4; nt++) {
                int col = nt * 8 + colLo;
                float2 bb = *(const float2*)(sBN + col);
                float x0 = gate[mi][nt][0] * fmaxf(c[mi][nt][0] + bb.x, 0.f);
                float x1 = gate[mi][nt][1] * fmaxf(c[mi][nt][1] + bb.y, 0.f);
                float x2 = gate[mi][nt][2] * fmaxf(c[mi][nt][2] + bb.x, 0.f);
                float x3 = gate[mi][nt][3] * fmaxf(c[mi][nt][3] + bb.y, 0.f);
                if (fast) {
                    if (rT < N_NODES) {
                        float* sp = sPool + (bT - gmin) * 128 + col;
                        atomicAdd(sp, x0); atomicAdd(sp + 1, x1);
                    }
                    if (rB < N_NODES) {
                        float* sp = sPool + (bB - gmin) * 128 + col;
                        atomicAdd(sp, x2); atomicAdd(sp + 1, x3);
                    }
                } else {
                    if (rT < N_NODES) red_add_v2(g_pooled + (size_t)bT * D_HID + col, x0, x1);
                    if (rB < N_NODES) red_add_v2(g_pooled + (size_t)bB * D_HID + col, x2, x3);
                }
            }
        }
        barg(barid);   // accumulation complete

        if (fast) {
            int ngr = gmax - gmin + 1;
            for (int i = ltid; i < ngr * 32; i += 256) {
                int g = i >> 5, c4 = (i & 31) * 4;
                const float* sp = sPool + g * 128 + c4;
                red_add_v4(g_pooled + (size_t)(gmin + g) * D_HID + c4,
                           sp[0], sp[1], sp[2], sp[3]);
            }
        }
        barg(barid);   // flush done before next tile's zero
    }
}

// ============================================================================
// Global block: 64 blocks x 256 threads, Wu + bu resident in SMEM.
// ============================================================================
__global__ __launch_bounds__(256) void global_kernel(
    const float* __restrict__ u, const float* __restrict__ Wu,
    const float* __restrict__ bu, float* __restrict__ out)
{
    extern __shared__ float gs[];
    float* sWu = gs;                         // 192 x 64
    float* sIn = gs + 192 * 64;              // 8 x 192
    float* sBu = gs + 192 * 64 + G_PER_BLK * 192;
    const int tid = threadIdx.x;
    const int gBase = blockIdx.x * G_PER_BLK;

    #pragma unroll
    for (int i = 0; i < 12; i++)
        ((float4*)sWu)[tid + i * 256] = __ldg((const float4*)Wu + tid + i * 256);
    if (tid < 64) sBu[tid] = bu[tid];

    for (int i = tid; i < G_PER_BLK * 192; i += 256) {
        int g = i / 192, k = i - g * 192;
        int gg = gBase + g;
        float v;
        if (k < D_GLOB) v = u[gg * D_GLOB + k];
        else {
            float cnt = fmaxf(g_counts[gg], 1.0f);
            v = g_pooled[gg * D_HID + (k - D_GLOB)] / cnt;
        }
        sIn[g * 192 + k] = v;
    }
    __syncthreads();

    #pragma unroll
    for (int o = 0; o < 2; o++) {
        int idx = tid + o * 256;
        int g = idx >> 6, j = idx & 63;
        const float* in = sIn + g * 192;
        float acc = sBu[j];
        #pragma unroll 8
        for (int k = 0; k < 192; k++)
            acc = fmaf(in[k], sWu[k * 64 + j], acc);
        out[(size_t)(gBase + g) * D_GLOB + j] = fmaxf(acc, 0.0f);
    }
}

// ---------------------------------------------------------------------------
extern "C" void kernel_launch(void* const* d_in, const int* in_sizes, int n_in,
                              void* d_out, int out_size)
{
    const float* x    = (const float*)d_in[0];
    const int*   eidx = (const int*)  d_in[1];
    const float* ea   = (const float*)d_in[2];
    const float* u    = (const float*)d_in[3];
    const int*   batch= (const int*)  d_in[4];
    const float* We1  = (const float*)d_in[5];
    const float* be1  = (const float*)d_in[6];
    const float* We2  = (const float*)d_in[7];
    const float* be2  = (const float*)d_in[8];
    const float* Wg   = (const float*)d_in[9];
    const float* bg   = (const float*)d_in[10];
    const float* Wn   = (const float*)d_in[11];
    const float* bn   = (const float*)d_in[12];
    const float* Wu   = (const float*)d_in[13];
    const float* bu   = (const float*)d_in[14];

    float* out   = (float*)d_out;
    float* u_new = out;
    float* xw    = out + N_GRAPHS * D_GLOB;

    cudaFuncSetAttribute(edge_kernel, cudaFuncAttributeMaxDynamicSharedMemorySize, E_TOTAL);
    cudaFuncSetAttribute(node_kernel, cudaFuncAttributeMaxDynamicSharedMemorySize, N_TOTAL);
    cudaFuncSetAttribute(global_kernel, cudaFuncAttributeMaxDynamicSharedMemorySize, G_SMEM);

    prep_all<<<2048, 256>>>(x, We1, We2, Wg, Wn, batch);
    edge_kernel<<<EDGE_GRID, ETHREADS, E_TOTAL>>>(eidx, ea, be1, be2);
    node_kernel<<<EDGE_GRID, ETHREADS, N_TOTAL>>>(batch, bg, bn, xw);
    global_kernel<<<N_GRAPHS / G_PER_BLK, 256, G_SMEM>>>(u, Wu, bu, u_new);
}

// round 17
// speedup vs baseline: 1.0884x; 1.0884x over previous
#include <cuda_runtime.h>
#include <cuda_fp16.h>
#include <math.h>
#include <stdint.h>

#define N_NODES 50000
#define N_EDGES 800000
#define N_GRAPHS 512
#define D_IN 128
#define D_EDGE 32
#define D_HID 128
#define D_GLOB 64
#define K1 288

#define TILE_E 64                  /* edge tile per warp-group */
#define NT (N_EDGES / TILE_E)      /* 12500 tiles */
#define TILE_N 64                  /* node tile per warp-group */
#define NTN ((N_NODES + TILE_N - 1) / TILE_N)  /* 782 */
#define EDGE_GRID 148
#define ETHREADS 512               /* 2 groups x 8 warps (2 wm x 4 wn, 32x32) */
#define NSTREAMS (EDGE_GRID * 2)   /* 296 tile streams */

#define A_STRIDE 296               /* halves: 592 B rows */
#define H_STRIDE 136               /* halves: 272 B rows */

// ---- scratch ----
__device__ float  g_agg[N_NODES * D_HID];
__device__ float  g_pooled[N_GRAPHS * D_HID];
__device__ float  g_counts[N_GRAPHS];
__device__ __half g_xh[N_NODES * D_IN];
// fp16 weight images: byte(k,n) = k*256 + (((n>>3)^(k&7))*16) + (n&7)*2
__device__ __half g_B1h[K1 * D_HID];
__device__ __half g_B2h[D_HID * D_HID];
__device__ __half g_Bgh[2 * D_HID * D_HID];
__device__ __half g_Bnh[2 * D_HID * D_HID];

// ---- edge kernel SMEM layout (bytes) ----
#define E_IDX   0                          /* 2 groups x 2 bufs x 128 ints = 2048 */
#define E_BE1   2048
#define E_BE2   2560
#define E_A     3072                       /* 2 groups x 64 x 592 = 75776 */
#define E_H     (E_A + 75776)              /* 78848: 2 groups x 64 x 272 = 34816 */
#define E_W1    (E_H + 34816)              /* 113664: 73728 */
#define E_W2    (E_W1 + 73728)             /* 187392: 32768 */
#define E_TOTAL (E_W2 + 32768)             /* 220160 */

#define A_GRP 37888
#define H_GRP 17408

// ---- node kernel SMEM layout (persistent) ----
#define N_BG    0
#define N_BN    512
#define N_A     1024                       /* 2 groups x 64 x 592 = 75776 */
#define N_WG    (N_A + 75776)
#define N_WN    (N_WG + 65536)
#define N_TOTAL (N_WN + 65536)             /* 207872 */

// ---- global kernel ----
#define G_PER_BLK 4
#define G_SMEM ((192 * 64 + G_PER_BLK * 192 + 64) * 4)

// ============================ PTX helpers ===================================
__device__ __forceinline__ uint32_t smem_u32(const void* p) {
    uint32_t a;
    asm("{ .reg .u64 t; cvta.to.shared.u64 t, %1; cvt.u32.u64 %0, t; }" : "=r"(a) : "l"(p));
    return a;
}
__device__ __forceinline__ void barg(int id) {
    asm volatile("bar.sync %0, %1;" :: "r"(id), "r"(256) : "memory");
}
__device__ __forceinline__ void ldm_x4(uint32_t* r, uint32_t addr) {
    asm volatile("ldmatrix.sync.aligned.m8n8.x4.shared.b16 {%0,%1,%2,%3}, [%4];"
                 : "=r"(r[0]), "=r"(r[1]), "=r"(r[2]), "=r"(r[3]) : "r"(addr));
}
__device__ __forceinline__ void ldm_x4_t(uint32_t* r, uint32_t addr) {
    asm volatile("ldmatrix.sync.aligned.m8n8.x4.trans.shared.b16 {%0,%1,%2,%3}, [%4];"
                 : "=r"(r[0]), "=r"(r[1]), "=r"(r[2]), "=r"(r[3]) : "r"(addr));
}
__device__ __forceinline__ void mma16816(float* c, const uint32_t* a, uint32_t b0, uint32_t b1) {
    asm volatile(
        "mma.sync.aligned.m16n8k16.row.col.f32.f16.f16.f32 "
        "{%0,%1,%2,%3}, {%4,%5,%6,%7}, {%8,%9}, {%0,%1,%2,%3};"
        : "+f"(c[0]), "+f"(c[1]), "+f"(c[2]), "+f"(c[3])
        : "r"(a[0]), "r"(a[1]), "r"(a[2]), "r"(a[3]), "r"(b0), "r"(b1));
}
__device__ __forceinline__ void red_add_v4(float* p, float a, float b, float c, float d) {
    asm volatile("red.global.add.v4.f32 [%0], {%1, %2, %3, %4};"
                 :: "l"(p), "f"(a), "f"(b), "f"(c), "f"(d) : "memory");
}
__device__ __forceinline__ void red_add_f(float* p, float a) {
    asm volatile("red.global.add.f32 [%0], %1;" :: "l"(p), "f"(a) : "memory");
}
__device__ __forceinline__ void cpa16(uint32_t dst, const void* src) {
    asm volatile("cp.async.cg.shared.global [%0], [%1], 16;" :: "r"(dst), "l"(src) : "memory");
}
#define CPA_COMMIT() asm volatile("cp.async.commit_group;" ::: "memory")
#define CPA_WAIT0()  asm volatile("cp.async.wait_group 0;" ::: "memory")
__device__ __forceinline__ uint32_t h2_bits(__half2 h) {
    return *reinterpret_cast<uint32_t*>(&h);
}

// ============================================================================
// Prep: zero scratch + fp16-convert x + weight images + counts histogram.
// ============================================================================
__global__ void prep_all(const float* __restrict__ x,
                         const float* __restrict__ We1, const float* __restrict__ We2,
                         const float* __restrict__ Wg,  const float* __restrict__ Wn,
                         const int* __restrict__ batch) {
    int idx = blockIdx.x * blockDim.x + threadIdx.x;
    int stride = gridDim.x * blockDim.x;
    float4 z = make_float4(0.f, 0.f, 0.f, 0.f);
    float4* a4 = (float4*)g_agg;
    for (int i = idx; i < N_NODES * D_HID / 4; i += stride) a4[i] = z;
    for (int i = idx; i < N_GRAPHS * D_HID; i += stride) g_pooled[i] = 0.0f;
    for (int i = idx; i < N_GRAPHS; i += stride) g_counts[i] = 0.0f;

    const int NX = N_NODES * D_IN / 4;
    for (int i = idx; i < NX; i += stride) {
        float4 v = __ldg((const float4*)x + i);
        __half2 h0 = __floats2half2_rn(v.x, v.y), h1 = __floats2half2_rn(v.z, v.w);
        *((uint2*)g_xh + i) = make_uint2(h2_bits(h0), h2_bits(h1));
    }
    for (int i = idx; i < K1 * D_HID; i += stride) {
        int k = i >> 7, n = i & 127;
        uint32_t off = (uint32_t)k * 256 + (((n >> 3) ^ (k & 7)) * 16) + (n & 7) * 2;
        *(__half*)((char*)g_B1h + off) = __float2half_rn(We1[k * D_HID + n]);
    }
    for (int i = idx; i < D_HID * D_HID; i += stride) {
        int k = i >> 7, n = i & 127;
        uint32_t off = (uint32_t)k * 256 + (((n >> 3) ^ (k & 7)) * 16) + (n & 7) * 2;
        *(__half*)((char*)g_B2h + off) = __float2half_rn(We2[k * D_HID + n]);
    }
    for (int i = idx; i < 2 * D_HID * D_HID; i += stride) {
        int k = i >> 7, n = i & 127;
        uint32_t off = (uint32_t)k * 256 + (((n >> 3) ^ (k & 7)) * 16) + (n & 7) * 2;
        *(__half*)((char*)g_Bgh + off) = __float2half_rn(Wg[k * D_HID + n]);
        *(__half*)((char*)g_Bnh + off) = __float2half_rn(Wn[k * D_HID + n]);
    }
    for (int i = idx; i < N_NODES; i += stride)
        red_add_f(&g_counts[batch[i]], 1.0f);
}

// ============================================================================
// Edge block: R15 champion — persistent, 2 independent 8-warp groups, resident
// weights, overlapped cp.async gather with inline ea conversion, v4 scatter.
// ============================================================================
__global__ __launch_bounds__(ETHREADS, 1) void edge_kernel(
    const int* __restrict__ eidx, const float* __restrict__ ea,
    const float* __restrict__ be1, const float* __restrict__ be2)
{
    extern __shared__ char smem[];
    const uint32_t sb = smem_u32(smem);
    const int tid = threadIdx.x, wid = tid >> 5, lane = tid & 31;
    const int grp = tid >> 8;
    const int lwid = wid & 7;
    const int ltid = tid & 255;
    const int wm = lwid & 1, wn = lwid >> 1;
    const int barid = grp + 1;

    int*   sIdx = (int*)(smem + E_IDX + grp * 1024);
    float* sBE1 = (float*)(smem + E_BE1);
    float* sBE2 = (float*)(smem + E_BE2);

    if (tid < D_HID) { sBE1[tid] = be1[tid]; sBE2[tid] = be2[tid]; }

    {
        const uint4* s1 = (const uint4*)g_B1h; uint4* d1 = (uint4*)(smem + E_W1);
        #pragma unroll
        for (int i = 0; i < 9; i++) d1[tid + i * 512] = s1[tid + i * 512];
        const uint4* s2 = (const uint4*)g_B2h; uint4* d2 = (uint4*)(smem + E_W2);
        #pragma unroll
        for (int i = 0; i < 4; i++) d2[tid + i * 512] = s2[tid + i * 512];
    }
    __syncthreads();

    const int lo15 = lane & 15;
    const int hi   = lane >> 4;
    const int lo7  = lane & 7;
    uint32_t bXor[2];
    #pragma unroll
    for (int p = 0; p < 2; p++) bXor[p] = (uint32_t)(((wn * 4 + 2 * p + hi) ^ lo7) * 16);

    const uint32_t aG = sb + E_A + grp * A_GRP;
    const uint32_t hG = sb + E_H + grp * H_GRP;
    const uint32_t aBase0 = aG + ((32 * wm + lo15) * A_STRIDE + hi * 8) * 2;
    const uint32_t aBase1 = aBase0 + 16 * A_STRIDE * 2;
    const uint32_t hBase0 = hG + ((32 * wm + lo15) * H_STRIDE + hi * 8) * 2;
    const uint32_t hBase1 = hBase0 + 16 * H_STRIDE * 2;
    const uint32_t w1Base = sb + E_W1 + lo15 * 256;
    const uint32_t w2Base = sb + E_W2 + lo15 * 256;

    const int rowLo = 32 * wm + (lane >> 2);
    const int colLo = wn * 32 + (lane & 3) * 2;
    const int odd   = lane & 1;
    const int col4  = wn * 32 + ((lane & 3) >> 1) * 4;

    const int eaRow = ltid >> 2, eaSeg = ltid & 3;
    const uint32_t eaDst = (aG - sb) + eaRow * 592 + 512 + eaSeg * 16;

    int t = blockIdx.x * 2 + grp;
    int pb = 0;
    if (ltid < TILE_E)            sIdx[ltid] = eidx[t * TILE_E + ltid];
    else if (ltid < 2 * TILE_E)   sIdx[ltid] = eidx[N_EDGES + t * TILE_E + (ltid - TILE_E)];
    barg(barid);
    {
        const float* ep = ea + (size_t)(t * TILE_E + eaRow) * D_EDGE + eaSeg * 8;
        float4 v0 = __ldg((const float4*)ep);
        float4 v1 = __ldg((const float4*)ep + 1);
        const int* sS = sIdx, *sD = sIdx + TILE_E;
        #pragma unroll
        for (int it = 0; it < 8; it++) {
            int i = ltid + it * 256;
            int row = i >> 5, u = i & 31;
            const void* src = (u < 16) ? (const void*)(g_xh + (size_t)sS[row] * D_IN + u * 8)
                                       : (const void*)(g_xh + (size_t)sD[row] * D_IN + (u - 16) * 8);
            cpa16(aG + row * 592 + u * 16, src);
        }
        CPA_COMMIT();
        *(uint2*)(smem + eaDst) = make_uint2(h2_bits(__floats2half2_rn(v0.x, v0.y)),
                                             h2_bits(__floats2half2_rn(v0.z, v0.w)));
        *(uint2*)(smem + eaDst + 8) = make_uint2(h2_bits(__floats2half2_rn(v1.x, v1.y)),
                                                 h2_bits(__floats2half2_rn(v1.z, v1.w)));
    }

    for (; t < NT; t += NSTREAMS, pb ^= 1) {
        const int tn = t + NSTREAMS;
        if (tn < NT) {
            if (ltid < TILE_E)          sIdx[(pb ^ 1) * 128 + ltid] = eidx[tn * TILE_E + ltid];
            else if (ltid < 2 * TILE_E) sIdx[(pb ^ 1) * 128 + ltid] =
                                            eidx[N_EDGES + tn * TILE_E + (ltid - TILE_E)];
        }
        CPA_WAIT0();
        barg(barid);

        float c[2][4][4];
        #pragma unroll
        for (int mi = 0; mi < 2; mi++)
            #pragma unroll
            for (int nt = 0; nt < 4; nt++)
                #pragma unroll
                for (int j = 0; j < 4; j++) c[mi][nt][j] = 0.0f;

        #pragma unroll
        for (int ks = 0; ks < 18; ks++) {
            uint32_t a0[4], a1[4];
            ldm_x4(a0, aBase0 + ks * 32);
            ldm_x4(a1, aBase1 + ks * 32);
            uint32_t bk = w1Base + ks * 4096;
            #pragma unroll
            for (int p = 0; p < 2; p++) {
                uint32_t b[4];
                ldm_x4_t(b, bk + bXor[p]);
                mma16816(c[0][2 * p + 0], a0, b[0], b[1]);
                mma16816(c[0][2 * p + 1], a0, b[2], b[3]);
                mma16816(c[1][2 * p + 0], a1, b[0], b[1]);
                mma16816(c[1][2 * p + 1], a1, b[2], b[3]);
            }
        }
        barg(barid);

        if (tn < NT) {
            const float* ep = ea + (size_t)(tn * TILE_E + eaRow) * D_EDGE + eaSeg * 8;
            float4 v0 = __ldg((const float4*)ep);
            float4 v1 = __ldg((const float4*)ep + 1);
            const int* sS = sIdx + (pb ^ 1) * 128, *sD = sS + TILE_E;
            #pragma unroll
            for (int it = 0; it < 8; it++) {
                int i = ltid + it * 256;
                int row = i >> 5, u = i & 31;
                const void* src = (u < 16) ? (const void*)(g_xh + (size_t)sS[row] * D_IN + u * 8)
                                           : (const void*)(g_xh + (size_t)sD[row] * D_IN + (u - 16) * 8);
                cpa16(aG + row * 592 + u * 16, src);
            }
            CPA_COMMIT();
            *(uint2*)(smem + eaDst) = make_uint2(h2_bits(__floats2half2_rn(v0.x, v0.y)),
                                                 h2_bits(__floats2half2_rn(v0.z, v0.w)));
            *(uint2*)(smem + eaDst + 8) = make_uint2(h2_bits(__floats2half2_rn(v1.x, v1.y)),
                                                     h2_bits(__floats2half2_rn(v1.z, v1.w)));
        }

        #pragma unroll
        for (int mi = 0; mi < 2; mi++) {
            int r0 = rowLo + 16 * mi;
            #pragma unroll
            for (int nt = 0; nt < 4; nt++) {
                int col = nt * 8 + colLo;
                float2 bb = *(const float2*)(sBE1 + col);
                float v0 = fmaxf(c[mi][nt][0] + bb.x, 0.f);
                float v1 = fmaxf(c[mi][nt][1] + bb.y, 0.f);
                float v2 = fmaxf(c[mi][nt][2] + bb.x, 0.f);
                float v3 = fmaxf(c[mi][nt][3] + bb.y, 0.f);
                *(uint32_t*)(smem + (hG - sb) + (r0 * H_STRIDE + col) * 2) =
                    h2_bits(__floats2half2_rn(v0, v1));
                *(uint32_t*)(smem + (hG - sb) + ((r0 + 8) * H_STRIDE + col) * 2) =
                    h2_bits(__floats2half2_rn(v2, v3));
            }
        }
        barg(barid);

        #pragma unroll
        for (int mi = 0; mi < 2; mi++)
            #pragma unroll
            for (int nt = 0; nt < 4; nt++)
                #pragma unroll
                for (int j = 0; j < 4; j++) c[mi][nt][j] = 0.0f;

        #pragma unroll
        for (int ks = 0; ks < 8; ks++) {
            uint32_t a0[4], a1[4];
            ldm_x4(a0, hBase0 + ks * 32);
            ldm_x4(a1, hBase1 + ks * 32);
            uint32_t bk = w2Base + ks * 4096;
            #pragma unroll
            for (int p = 0; p < 2; p++) {
                uint32_t b[4];
                ldm_x4_t(b, bk + bXor[p]);
                mma16816(c[0][2 * p + 0], a0, b[0], b[1]);
                mma16816(c[0][2 * p + 1], a0, b[2], b[3]);
                mma16816(c[1][2 * p + 0], a1, b[0], b[1]);
                mma16816(c[1][2 * p + 1], a1, b[2], b[3]);
            }
        }

        const int* sDstP = sIdx + pb * 128 + TILE_E;
        #pragma unroll
        for (int mi = 0; mi < 2; mi++) {
            int rT = rowLo + 16 * mi;
            int rB = rT + 8;
            float* dp = g_agg + (size_t)sDstP[odd ? rB : rT] * D_HID;
            #pragma unroll
            for (int nt = 0; nt < 4; nt++) {
                int col = nt * 8 + colLo;
                float2 bb = *(const float2*)(sBE2 + col);
                float t0 = fmaxf(c[mi][nt][0] + bb.x, 0.f);
                float t1 = fmaxf(c[mi][nt][1] + bb.y, 0.f);
                float b0 = fmaxf(c[mi][nt][2] + bb.x, 0.f);
                float b1 = fmaxf(c[mi][nt][3] + bb.y, 0.f);
                float2 send = odd ? make_float2(t0, t1) : make_float2(b0, b1);
                unsigned long long sv = *reinterpret_cast<unsigned long long*>(&send);
                unsigned long long rvu = __shfl_xor_sync(0xffffffffu, sv, 1);
                float2 rv = *reinterpret_cast<float2*>(&rvu);
                if (!odd) red_add_v4(dp + nt * 8 + col4, t0, t1, rv.x, rv.y);
                else      red_add_v4(dp + nt * 8 + col4, rv.x, rv.y, b0, b1);
            }
        }
    }
}

// ============================================================================
// Node block: R15 persistent version + v4 pair-shuffle pooled scatter.
// ============================================================================
__global__ __launch_bounds__(ETHREADS, 1) void node_kernel(
    const int* __restrict__ batch,
    const float* __restrict__ bg, const float* __restrict__ bn,
    float* __restrict__ xw_out)
{
    extern __shared__ char smem[];
    const uint32_t sb = smem_u32(smem);
    const int tid = threadIdx.x, wid = tid >> 5, lane = tid & 31;
    const int grp = tid >> 8;
    const int lwid = wid & 7;
    const int ltid = tid & 255;
    const int wm = lwid & 1, wn = lwid >> 1;
    const int barid = grp + 1;

    float* sBG = (float*)(smem + N_BG);
    float* sBN = (float*)(smem + N_BN);
    if (tid < D_HID) { sBG[tid] = bg[tid]; sBN[tid] = bn[tid]; }

    {
        const uint4* sg = (const uint4*)g_Bgh; uint4* dg = (uint4*)(smem + N_WG);
        #pragma unroll
        for (int i = 0; i < 8; i++) dg[tid + i * 512] = sg[tid + i * 512];
        const uint4* sn = (const uint4*)g_Bnh; uint4* dn = (uint4*)(smem + N_WN);
        #pragma unroll
        for (int i = 0; i < 8; i++) dn[tid + i * 512] = sn[tid + i * 512];
    }
    __syncthreads();

    const int lo15 = lane & 15;
    const int hi   = lane >> 4;
    const int lo7  = lane & 7;
    uint32_t bXor[2];
    #pragma unroll
    for (int p = 0; p < 2; p++) bXor[p] = (uint32_t)(((wn * 4 + 2 * p + hi) ^ lo7) * 16);

    const uint32_t aG = sb + N_A + grp * A_GRP;
    const uint32_t aBase0 = aG + ((32 * wm + lo15) * A_STRIDE + hi * 8) * 2;
    const uint32_t aBase1 = aBase0 + 16 * A_STRIDE * 2;
    const uint32_t wgBase = sb + N_WG + lo15 * 256;
    const uint32_t wnBase = sb + N_WN + lo15 * 256;

    const int rowLo = 32 * wm + (lane >> 2);
    const int colLo = wn * 32 + (lane & 3) * 2;
    const int odd   = lane & 1;
    const int col4  = wn * 32 + ((lane & 3) >> 1) * 4;

    for (int t = blockIdx.x * 2 + grp; t < NTN; t += NSTREAMS) {
        const int nBase = t * TILE_N;

        #pragma unroll
        for (int it = 0; it < 8; it++) {
            int i = ltid + it * 256;
            int row = i >> 5, u = i & 31;
            int n = min(nBase + row, N_NODES - 1);
            if (u < 16) {
                cpa16(aG + row * 592 + u * 16, g_xh + (size_t)n * D_IN + u * 8);
            } else {
                const float4* ap = (const float4*)(g_agg + (size_t)n * D_HID + (u - 16) * 8);
                float4 v0 = ap[0], v1 = ap[1];
                uint4 o;
                o.x = h2_bits(__floats2half2_rn(v0.x, v0.y));
                o.y = h2_bits(__floats2half2_rn(v0.z, v0.w));
                o.z = h2_bits(__floats2half2_rn(v1.x, v1.y));
                o.w = h2_bits(__floats2half2_rn(v1.z, v1.w));
                *reinterpret_cast<uint4*>(smem + (aG - sb) + row * 592 + u * 16) = o;
            }
        }
        CPA_COMMIT();
        CPA_WAIT0();
        barg(barid);

        float c[2][4][4];
        #pragma unroll
        for (int mi = 0; mi < 2; mi++)
            #pragma unroll
            for (int nt = 0; nt < 4; nt++)
                #pragma unroll
                for (int j = 0; j < 4; j++) c[mi][nt][j] = 0.0f;

        #pragma unroll
        for (int ks = 0; ks < 16; ks++) {
            uint32_t a0[4], a1[4];
            ldm_x4(a0, aBase0 + ks * 32);
            ldm_x4(a1, aBase1 + ks * 32);
            uint32_t bk = wgBase + ks * 4096;
            #pragma unroll
            for (int p = 0; p < 2; p++) {
                uint32_t b[4];
                ldm_x4_t(b, bk + bXor[p]);
                mma16816(c[0][2 * p + 0], a0, b[0], b[1]);
                mma16816(c[0][2 * p + 1], a0, b[2], b[3]);
                mma16816(c[1][2 * p + 0], a1, b[0], b[1]);
                mma16816(c[1][2 * p + 1], a1, b[2], b[3]);
            }
        }

        float gate[2][4][4];
        #pragma unroll
        for (int mi = 0; mi < 2; mi++) {
            int rT = nBase + rowLo + 16 * mi;
            int rB = rT + 8;
            #pragma unroll
            for (int nt = 0; nt < 4; nt++) {
                int col = nt * 8 + colLo;
                float2 bb = *(const float2*)(sBG + col);
                gate[mi][nt][0] = 1.0f / (1.0f + __expf(-(c[mi][nt][0] + bb.x)));
                gate[mi][nt][1] = 1.0f / (1.0f + __expf(-(c[mi][nt][1] + bb.y)));
                gate[mi][nt][2] = 1.0f / (1.0f + __expf(-(c[mi][nt][2] + bb.x)));
                gate[mi][nt][3] = 1.0f / (1.0f + __expf(-(c[mi][nt][3] + bb.y)));
                if (rT < N_NODES)
                    *(float2*)(xw_out + (size_t)rT * D_HID + col) =
                        make_float2(gate[mi][nt][0], gate[mi][nt][1]);
                if (rB < N_NODES)
                    *(float2*)(xw_out + (size_t)rB * D_HID + col) =
                        make_float2(gate[mi][nt][2], gate[mi][nt][3]);
            }
        }

        #pragma unroll
        for (int mi = 0; mi < 2; mi++)
            #pragma unroll
            for (int nt = 0; nt < 4; nt++)
                #pragma unroll
                for (int j = 0; j < 4; j++) c[mi][nt][j] = 0.0f;

        #pragma unroll
        for (int ks = 0; ks < 16; ks++) {
            uint32_t a0[4], a1[4];
            ldm_x4(a0, aBase0 + ks * 32);
            ldm_x4(a1, aBase1 + ks * 32);
            uint32_t bk = wnBase + ks * 4096;
            #pragma unroll
            for (int p = 0; p < 2; p++) {
                uint32_t b[4];
                ldm_x4_t(b, bk + bXor[p]);
                mma16816(c[0][2 * p + 0], a0, b[0], b[1]);
                mma16816(c[0][2 * p + 1], a0, b[2], b[3]);
                mma16816(c[1][2 * p + 0], a1, b[0], b[1]);
                mma16816(c[1][2 * p + 1], a1, b[2], b[3]);
            }
        }

        // x_new epilogue: pair-shuffle -> v4 pooled scatter (bounds via guard)
        #pragma unroll
        for (int mi = 0; mi < 2; mi++) {
            int rT = nBase + rowLo + 16 * mi;
            int rB = rT + 8;
            int bT = batch[min(rT, N_NODES - 1)];
            int bB = batch[min(rB, N_NODES - 1)];
            int myR   = odd ? rB : rT;
            float* dp = g_pooled + (size_t)(odd ? bB : bT) * D_HID;
            #pragma unroll
            for (int nt = 0; nt < 4; nt++) {
                int col = nt * 8 + colLo;
                float2 bb = *(const float2*)(sBN + col);
                float x0 = (rT < N_NODES) ? gate[mi][nt][0] * fmaxf(c[mi][nt][0] + bb.x, 0.f) : 0.f;
                float x1 = (rT < N_NODES) ? gate[mi][nt][1] * fmaxf(c[mi][nt][1] + bb.y, 0.f) : 0.f;
                float x2 = (rB < N_NODES) ? gate[mi][nt][2] * fmaxf(c[mi][nt][2] + bb.x, 0.f) : 0.f;
                float x3 = (rB < N_NODES) ? gate[mi][nt][3] * fmaxf(c[mi][nt][3] + bb.y, 0.f) : 0.f;
                float2 send = odd ? make_float2(x0, x1) : make_float2(x2, x3);
                unsigned long long sv = *reinterpret_cast<unsigned long long*>(&send);
                unsigned long long rvu = __shfl_xor_sync(0xffffffffu, sv, 1);
                float2 rv = *reinterpret_cast<float2*>(&rvu);
                if (myR < N_NODES) {
                    if (!odd) red_add_v4(dp + nt * 8 + col4, x0, x1, rv.x, rv.y);
                    else      red_add_v4(dp + nt * 8 + col4, rv.x, rv.y, x2, x3);
                }
            }
        }
        barg(barid);
    }
}

// ============================================================================
// Global block: 128 blocks x 256 threads, 4 graphs/block, Wu+bu in SMEM.
// ============================================================================
__global__ __launch_bounds__(256) void global_kernel(
    const float* __restrict__ u, const float* __restrict__ Wu,
    const float* __restrict__ bu, float* __restrict__ out)
{
    extern __shared__ float gs[];
    float* sWu = gs;                         // 192 x 64
    float* sIn = gs + 192 * 64;              // 4 x 192
    float* sBu = gs + 192 * 64 + G_PER_BLK * 192;
    const int tid = threadIdx.x;
    const int gBase = blockIdx.x * G_PER_BLK;

    #pragma unroll
    for (int i = 0; i < 12; i++)
        ((float4*)sWu)[tid + i * 256] = __ldg((const float4*)Wu + tid + i * 256);
    if (tid < 64) sBu[tid] = bu[tid];

    for (int i = tid; i < G_PER_BLK * 192; i += 256) {
        int g = i / 192, k = i - g * 192;
        int gg = gBase + g;
        float v;
        if (k < D_GLOB) v = u[gg * D_GLOB + k];
        else {
            float cnt = fmaxf(g_counts[gg], 1.0f);
            v = g_pooled[gg * D_HID + (k - D_GLOB)] / cnt;
        }
        sIn[g * 192 + k] = v;
    }
    __syncthreads();

    {
        int g = tid >> 6, j = tid & 63;
        const float* in = sIn + g * 192;
        float acc = sBu[j];
        #pragma unroll 8
        for (int k = 0; k < 192; k++)
            acc = fmaf(in[k], sWu[k * 64 + j], acc);
        out[(size_t)(gBase + g) * D_GLOB + j] = fmaxf(acc, 0.0f);
    }
}

// ---------------------------------------------------------------------------
extern "C" void kernel_launch(void* const* d_in, const int* in_sizes, int n_in,
                              void* d_out, int out_size)
{
    const float* x    = (const float*)d_in[0];
    const int*   eidx = (const int*)  d_in[1];
    const float* ea   = (const float*)d_in[2];
    const float* u    = (const float*)d_in[3];
    const int*   batch= (const int*)  d_in[4];
    const float* We1  = (const float*)d_in[5];
    const float* be1  = (const float*)d_in[6];
    const float* We2  = (const float*)d_in[7];
    const float* be2  = (const float*)d_in[8];
    const float* Wg   = (const float*)d_in[9];
    const float* bg   = (const float*)d_in[10];
    const float* Wn   = (const float*)d_in[11];
    const float* bn   = (const float*)d_in[12];
    const float* Wu   = (const float*)d_in[13];
    const float* bu   = (const float*)d_in[14];

    float* out   = (float*)d_out;
    float* u_new = out;
    float* xw    = out + N_GRAPHS * D_GLOB;

    cudaFuncSetAttribute(edge_kernel, cudaFuncAttributeMaxDynamicSharedMemorySize, E_TOTAL);
    cudaFuncSetAttribute(node_kernel, cudaFuncAttributeMaxDynamicSharedMemorySize, N_TOTAL);
    cudaFuncSetAttribute(global_kernel, cudaFuncAttributeMaxDynamicSharedMemorySize, G_SMEM);

    prep_all<<<2048, 256>>>(x, We1, We2, Wg, Wn, batch);
    edge_kernel<<<EDGE_GRID, ETHREADS, E_TOTAL>>>(eidx, ea, be1, be2);
    node_kernel<<<EDGE_GRID, ETHREADS, N_TOTAL>>>(batch, bg, bn, xw);
    global_kernel<<<N_GRAPHS / G_PER_BLK, 256, G_SMEM>>>(u, Wu, bu, u_new);
}